// round 1
// baseline (speedup 1.0000x reference)
#include <cuda_runtime.h>
#include <cuda_fp16.h>

#define R    8192
#define D    64
#define TW   1000
#define TTOT 2000
#define NB   256
#define NT   256
#define RPC  32   // rows per CTA
#define RPW  4    // rows per warp

// d_out layout (float32), reference return order:
// prediction[1000,64], target[1000,64], prediction_augment[2000,64], target_augment[2000,64]
#define PRED_OFF 0
#define TGT_OFF  (1000*64)
#define PA_OFF   (2*1000*64)
#define TA_OFF   (4*1000*64)

static_assert(NB * RPC == R, "row partition");
static_assert(NT == 8 * 32, "8 warps");

// ---------------- device state (static scratch; no allocations) ----------------
__device__ __half  d_Wh16[(size_t)R * R];   // 128 MB fp16 copy of W_h
__device__ float   d_WoutT[(size_t)R * D];  // W_out transposed: [r][i]
__device__ float   d_h[2][R];               // ping-pong hidden state
__device__ float   d_obuf[3][D];            // triple-buffered readout accumulator
__device__ unsigned d_bar_count;
__device__ unsigned d_bar_gen;

// ---------------- prologue: fp32 -> fp16 weight conversion ----------------
__global__ void k_convert(const float* __restrict__ Wh) {
    size_t n = (size_t)R * R / 8;
    const float4* src = (const float4*)Wh;
    uint4* dst = (uint4*)d_Wh16;
    for (size_t i = (size_t)blockIdx.x * blockDim.x + threadIdx.x; i < n;
         i += (size_t)gridDim.x * blockDim.x) {
        float4 a = src[2 * i], b = src[2 * i + 1];
        __half2 p0 = __floats2half2_rn(a.x, a.y);
        __half2 p1 = __floats2half2_rn(a.z, a.w);
        __half2 p2 = __floats2half2_rn(b.x, b.y);
        __half2 p3 = __floats2half2_rn(b.z, b.w);
        uint4 o;
        o.x = *reinterpret_cast<unsigned*>(&p0);
        o.y = *reinterpret_cast<unsigned*>(&p1);
        o.z = *reinterpret_cast<unsigned*>(&p2);
        o.w = *reinterpret_cast<unsigned*>(&p3);
        dst[i] = o;
    }
}

// ---------------- prologue: transpose W_out, copy targets, init state ----------------
__global__ void k_prep(const float* __restrict__ Wout,
                       const float* __restrict__ xin,
                       float* __restrict__ out) {
    int tid = blockIdx.x * blockDim.x + threadIdx.x;
    int stride = gridDim.x * blockDim.x;
    for (int i = tid; i < R * D; i += stride) {
        int r = i / D, c = i % D;
        d_WoutT[i] = Wout[(size_t)c * R + r];
    }
    for (int i = tid; i < TTOT * D; i += stride) {
        float v = xin[i];
        out[TA_OFF + i] = v;
        if (i >= TW * D) out[TGT_OFF + i - TW * D] = v;
    }
    for (int i = tid; i < R; i += stride) { d_h[0][i] = 0.f; d_h[1][i] = 0.f; }
    if (tid < 3 * D) ((float*)d_obuf)[tid] = 0.f;
    if (tid == 0) { d_bar_count = 0; d_bar_gen = 0; }
}

// ---------------- grid barrier (sense via generation counter) ----------------
__device__ __forceinline__ void gridbar() {
    __threadfence();
    __syncthreads();
    if (threadIdx.x == 0) {
        volatile unsigned* vgen = (volatile unsigned*)&d_bar_gen;
        unsigned g = *vgen;                      // read BEFORE arriving
        unsigned a = atomicAdd(&d_bar_count, 1u);
        if (a == NB - 1) {
            *(volatile unsigned*)&d_bar_count = 0;
            __threadfence();
            *vgen = g + 1;
        } else {
            while (*vgen == g) { }
        }
        __threadfence();
    }
    __syncthreads();
}

__device__ __forceinline__ float dot8(uint4 q, float4 ha, float4 hb) {
    __half2* h2 = reinterpret_cast<__half2*>(&q);
    float2 f0 = __half22float2(h2[0]);
    float2 f1 = __half22float2(h2[1]);
    float2 f2 = __half22float2(h2[2]);
    float2 f3 = __half22float2(h2[3]);
    return f0.x * ha.x + f0.y * ha.y + f1.x * ha.z + f1.y * ha.w +
           f2.x * hb.x + f2.y * hb.y + f3.x * hb.z + f3.y * hb.w;
}

// ---------------- persistent ESN kernel ----------------
__global__ void __launch_bounds__(NT, 2)
k_esn(const float* __restrict__ xin,   // input_sequence [2000,64]
      const float* __restrict__ Win,   // [8192,64]
      float* __restrict__ out) {
    __shared__ float h_sh[R];          // 32 KB: full hidden state
    __shared__ float x_sh[D];
    __shared__ float ored[8 * 64];     // per-warp readout partials

    const int tid = threadIdx.x;
    const int lane = tid & 31;
    const int warp = tid >> 5;
    const int cta = blockIdx.x;
    const int grow0 = cta * RPC + warp * RPW;   // first global row of this warp

    const uint4* w0 = (const uint4*)(d_Wh16 + (size_t)(grow0 + 0) * R);
    const uint4* w1 = (const uint4*)(d_Wh16 + (size_t)(grow0 + 1) * R);
    const uint4* w2 = (const uint4*)(d_Wh16 + (size_t)(grow0 + 2) * R);
    const uint4* w3 = (const uint4*)(d_Wh16 + (size_t)(grow0 + 3) * R);
    const float* winr = Win + (size_t)grow0 * D + 2 * lane;
    const float* wt = d_WoutT + (size_t)grow0 * D;

    for (int s = 0; s < TTOT; ++s) {
        // ---- publish outputs of previous step, zero future buffer, fetch x ----
        if (tid < D) {
            if (cta == 0) {
                float v = d_obuf[s % 3][tid];   // = W_out @ aug(h_s)
                if (s >= 1 && s <= TW) out[PA_OFF + (s - 1) * D + tid] = v;
                if (s >= TW) {
                    out[PRED_OFF + (s - TW) * D + tid] = v;
                    out[PA_OFF + s * D + tid] = v;
                }
                d_obuf[(s + 2) % 3][tid] = 0.f;  // recycle oldest buffer
            }
            x_sh[tid] = (s < TW) ? xin[(size_t)s * D + tid] : d_obuf[s % 3][tid];
        }
        // ---- load h_s into shared ----
        const float4* hsrc = (const float4*)d_h[s & 1];
        for (int i = tid; i < R / 4; i += NT) ((float4*)h_sh)[i] = hsrc[i];
        __syncthreads();

        // ---- W_h @ h  (4 rows per warp, serpentine k order for L2 reuse) ----
        float acc0 = 0.f, acc1 = 0.f, acc2 = 0.f, acc3 = 0.f;
        const bool rev = (s & 1);
        #pragma unroll 4
        for (int it = 0; it < 32; ++it) {
            int itt = rev ? (31 - it) : it;
            int k = itt * 256 + lane * 8;
            int widx = itt * 32 + lane;
            float4 ha = *(const float4*)(h_sh + k);
            float4 hb = *(const float4*)(h_sh + k + 4);
            uint4 q0 = w0[widx];
            uint4 q1 = w1[widx];
            uint4 q2 = w2[widx];
            uint4 q3 = w3[widx];
            acc0 += dot8(q0, ha, hb);
            acc1 += dot8(q1, ha, hb);
            acc2 += dot8(q2, ha, hb);
            acc3 += dot8(q3, ha, hb);
        }
        // ---- + W_in @ x (2 x-elements per lane, folded into same reduction) ----
        {
            float xa = x_sh[2 * lane], xb = x_sh[2 * lane + 1];
            acc0 += winr[0]         * xa + winr[1]         * xb;
            acc1 += winr[D]         * xa + winr[D + 1]     * xb;
            acc2 += winr[2 * D]     * xa + winr[2 * D + 1] * xb;
            acc3 += winr[3 * D]     * xa + winr[3 * D + 1] * xb;
        }
        #pragma unroll
        for (int o = 16; o; o >>= 1) {
            acc0 += __shfl_xor_sync(0xffffffffu, acc0, o);
            acc1 += __shfl_xor_sync(0xffffffffu, acc1, o);
            acc2 += __shfl_xor_sync(0xffffffffu, acc2, o);
            acc3 += __shfl_xor_sync(0xffffffffu, acc3, o);
        }
        // ---- tanh, store h_{s+1}, aug() broadcast ----
        float a0 = 0.f, a1 = 0.f, a2 = 0.f, a3 = 0.f;
        if (lane == 0) {
            float h0 = tanhf(acc0), h1 = tanhf(acc1), h2 = tanhf(acc2), h3 = tanhf(acc3);
            *(float4*)(d_h[(s + 1) & 1] + grow0) = make_float4(h0, h1, h2, h3);
            a0 = h0 * h0;  // grow0 % 4 == 0 -> even row: square
            a1 = h1;       // odd row: identity
            a2 = h2 * h2;
            a3 = h3;
        }
        a0 = __shfl_sync(0xffffffffu, a0, 0);
        a1 = __shfl_sync(0xffffffffu, a1, 0);
        a2 = __shfl_sync(0xffffffffu, a2, 0);
        a3 = __shfl_sync(0xffffffffu, a3, 0);

        // ---- fused readout partials: W_out @ aug(h_{s+1}) for this warp's rows ----
        float p0 = wt[lane]          * a0 + wt[D + lane]          * a1 +
                   wt[2 * D + lane]  * a2 + wt[3 * D + lane]      * a3;
        float p1 = wt[32 + lane]     * a0 + wt[D + 32 + lane]     * a1 +
                   wt[2 * D + 32 + lane] * a2 + wt[3 * D + 32 + lane] * a3;
        ored[warp * 64 + lane] = p0;
        ored[warp * 64 + 32 + lane] = p1;
        __syncthreads();
        if (tid < D) {
            float sum = 0.f;
            #pragma unroll
            for (int w = 0; w < 8; ++w) sum += ored[w * 64 + tid];
            atomicAdd(&d_obuf[(s + 1) % 3][tid], sum);
        }
        gridbar();  // publishes h_{s+1} and out(h_{s+1}) grid-wide
    }
}

// ---------------- launch ----------------
extern "C" void kernel_launch(void* const* d_in, const int* in_sizes, int n_in,
                              void* d_out, int out_size) {
    const float* xin  = (const float*)d_in[0];  // input_sequence
    const float* Win  = (const float*)d_in[1];  // W_in
    const float* Whf  = (const float*)d_in[2];  // W_h (fp32)
    const float* Wout = (const float*)d_in[3];  // W_out
    float* out = (float*)d_out;

    k_convert<<<4096, 256>>>(Whf);
    k_prep<<<1024, 256>>>(Wout, xin, out);
    k_esn<<<NB, NT>>>(xin, Win, out);
}

// round 2
// speedup vs baseline: 1.1102x; 1.1102x over previous
#include <cuda_runtime.h>
#include <cuda_fp16.h>

#define R     8192
#define D     64
#define TW    1000
#define TTOT  2000
#define NB    128     // CTAs (1 per SM, 152 SMs available)
#define NT    512     // threads per CTA (16 warps)
#define WARPS 16
#define RPW   4       // rows per warp
#define RPC   64      // rows per CTA
#define SROWS 8       // rows cached in SMEM per CTA (warps 0,1)

// d_out layout (float32): prediction[1000,64], target[1000,64],
// prediction_augment[2000,64], target_augment[2000,64]
#define PRED_OFF 0
#define TGT_OFF  (1000*64)
#define PA_OFF   (2*1000*64)
#define TA_OFF   (4*1000*64)

static_assert(NB * RPC == R, "row partition");
static_assert(NT == WARPS * 32, "warps");

// ---------------- device state ----------------
__device__ __half  d_Wh16[(size_t)R * R];   // 128 MB fp16 W_h
__device__ float   d_WoutT[(size_t)R * D];  // W_out transposed [r][i]
__device__ float   d_h[2][R];               // ping-pong hidden state
__device__ float   d_osub[3][8][D];         // triple-buffered, 8-way split readout accum
__device__ unsigned d_bar_count;
__device__ unsigned d_bar_gen;

// ---------------- prologue: fp32 -> fp16 weights ----------------
__global__ void k_convert(const float* __restrict__ Wh) {
    size_t n = (size_t)R * R / 8;
    const float4* src = (const float4*)Wh;
    uint4* dst = (uint4*)d_Wh16;
    for (size_t i = (size_t)blockIdx.x * blockDim.x + threadIdx.x; i < n;
         i += (size_t)gridDim.x * blockDim.x) {
        float4 a = src[2 * i], b = src[2 * i + 1];
        __half2 p0 = __floats2half2_rn(a.x, a.y);
        __half2 p1 = __floats2half2_rn(a.z, a.w);
        __half2 p2 = __floats2half2_rn(b.x, b.y);
        __half2 p3 = __floats2half2_rn(b.z, b.w);
        uint4 o;
        o.x = *reinterpret_cast<unsigned*>(&p0);
        o.y = *reinterpret_cast<unsigned*>(&p1);
        o.z = *reinterpret_cast<unsigned*>(&p2);
        o.w = *reinterpret_cast<unsigned*>(&p3);
        dst[i] = o;
    }
}

// ---------------- prologue: transpose W_out, copy targets, init ----------------
__global__ void k_prep(const float* __restrict__ Wout,
                       const float* __restrict__ xin,
                       float* __restrict__ out) {
    int tid = blockIdx.x * blockDim.x + threadIdx.x;
    int stride = gridDim.x * blockDim.x;
    for (int i = tid; i < R * D; i += stride) {
        int r = i / D, c = i % D;
        d_WoutT[i] = Wout[(size_t)c * R + r];
    }
    for (int i = tid; i < TTOT * D; i += stride) {
        float v = xin[i];
        out[TA_OFF + i] = v;
        if (i >= TW * D) out[TGT_OFF + i - TW * D] = v;
    }
    for (int i = tid; i < R; i += stride) { d_h[0][i] = 0.f; d_h[1][i] = 0.f; }
    if (tid < 3 * 8 * D) ((float*)d_osub)[tid] = 0.f;
    if (tid == 0) { d_bar_count = 0; d_bar_gen = 0; }
}

// ---------------- grid barrier ----------------
__device__ __forceinline__ void gridbar() {
    __threadfence();
    __syncthreads();
    if (threadIdx.x == 0) {
        volatile unsigned* vgen = (volatile unsigned*)&d_bar_gen;
        unsigned g = *vgen;
        unsigned a = atomicAdd(&d_bar_count, 1u);
        if (a == NB - 1) {
            *(volatile unsigned*)&d_bar_count = 0;
            __threadfence();
            *vgen = g + 1;
        } else {
            while (*vgen == g) { }
        }
        __threadfence();
    }
    __syncthreads();
}

__device__ __forceinline__ float dot8(uint4 q, float4 ha, float4 hb) {
    __half2* h2 = reinterpret_cast<__half2*>(&q);
    float2 f0 = __half22float2(h2[0]);
    float2 f1 = __half22float2(h2[1]);
    float2 f2 = __half22float2(h2[2]);
    float2 f3 = __half22float2(h2[3]);
    return f0.x * ha.x + f0.y * ha.y + f1.x * ha.z + f1.y * ha.w +
           f2.x * hb.x + f2.y * hb.y + f3.x * hb.z + f3.y * hb.w;
}

// dynamic smem layout
#define SM_WC    0                               // SROWS*8192 halves = 131072 B
#define SM_H     (SROWS * R * 2)                 // 8192 floats = 32768 B
#define SM_ORED  (SM_H + R * 4)                  // WARPS*64 floats = 4096 B
#define SM_X     (SM_ORED + WARPS * 64 * 4)      // 64 floats
#define SM_TOTAL (SM_X + 64 * 4)                 // 168448 B

// ---------------- persistent ESN kernel ----------------
__global__ void __launch_bounds__(NT, 1)
k_esn(const float* __restrict__ xin,
      const float* __restrict__ Win,
      float* __restrict__ out) {
    extern __shared__ char smem[];
    __half* wc   = (__half*)(smem + SM_WC);
    float*  h_sh = (float*)(smem + SM_H);
    float*  ored = (float*)(smem + SM_ORED);
    float*  x_sh = (float*)(smem + SM_X);

    const int tid  = threadIdx.x;
    const int lane = tid & 31;
    const int warp = tid >> 5;
    const int cta  = blockIdx.x;
    const int grow0 = cta * RPC + warp * RPW;    // first global row of this warp

    // ---- pin first SROWS rows of this CTA's slice in SMEM ----
    {
        const uint4* src = (const uint4*)(d_Wh16 + (size_t)cta * RPC * R);
        uint4* dst = (uint4*)wc;
        for (int i = tid; i < SROWS * (R / 8); i += NT) dst[i] = src[i];
    }

    const uint4* w0 = (const uint4*)(d_Wh16 + (size_t)(grow0 + 0) * R);
    const uint4* w1 = (const uint4*)(d_Wh16 + (size_t)(grow0 + 1) * R);
    const uint4* w2 = (const uint4*)(d_Wh16 + (size_t)(grow0 + 2) * R);
    const uint4* w3 = (const uint4*)(d_Wh16 + (size_t)(grow0 + 3) * R);
    const uint4* c0 = (const uint4*)(wc + (size_t)(warp * RPW + 0) * R);
    const uint4* c1 = (const uint4*)(wc + (size_t)(warp * RPW + 1) * R);
    const uint4* c2 = (const uint4*)(wc + (size_t)(warp * RPW + 2) * R);
    const uint4* c3 = (const uint4*)(wc + (size_t)(warp * RPW + 3) * R);
    const float* winr = Win + (size_t)grow0 * D + 2 * lane;
    const float* wt = d_WoutT + (size_t)grow0 * D;
    __syncthreads();

    for (int s = 0; s < TTOT; ++s) {
        // ---- publish out(h_s), prepare x, recycle buffers ----
        if (tid < D) {
            float o = 0.f;
            if (cta == 0 || s >= TW) {
                #pragma unroll
                for (int b = 0; b < 8; ++b) o += d_osub[s % 3][b][tid];
            }
            if (cta == 0) {
                if (s >= 1 && s <= TW) out[PA_OFF + (s - 1) * D + tid] = o;
                if (s >= TW) {
                    out[PRED_OFF + (s - TW) * D + tid] = o;
                    out[PA_OFF + s * D + tid] = o;
                }
            }
            if (cta < 8) d_osub[(s + 2) % 3][cta][tid] = 0.f;
            x_sh[tid] = (s < TW) ? xin[(size_t)s * D + tid] : o;
        }
        // ---- load h_s into shared ----
        {
            const float4* hsrc = (const float4*)d_h[s & 1];
            for (int i = tid; i < R / 4; i += NT) ((float4*)h_sh)[i] = hsrc[i];
        }
        __syncthreads();

        // ---- W_h @ h : warps 0,1 from SMEM cache, warps 2..15 from L2 ----
        float acc0 = 0.f, acc1 = 0.f, acc2 = 0.f, acc3 = 0.f;
        if (warp < SROWS / RPW) {
            #pragma unroll 4
            for (int it = 0; it < 32; ++it) {
                int k = it * 256 + lane * 8;
                int widx = it * 32 + lane;
                float4 ha = *(const float4*)(h_sh + k);
                float4 hb = *(const float4*)(h_sh + k + 4);
                uint4 q0 = c0[widx];
                uint4 q1 = c1[widx];
                uint4 q2 = c2[widx];
                uint4 q3 = c3[widx];
                acc0 += dot8(q0, ha, hb);
                acc1 += dot8(q1, ha, hb);
                acc2 += dot8(q2, ha, hb);
                acc3 += dot8(q3, ha, hb);
            }
        } else {
            const bool rev = (s & 1);
            #pragma unroll 4
            for (int it = 0; it < 32; ++it) {
                int itt = rev ? (31 - it) : it;
                int k = itt * 256 + lane * 8;
                int widx = itt * 32 + lane;
                float4 ha = *(const float4*)(h_sh + k);
                float4 hb = *(const float4*)(h_sh + k + 4);
                uint4 q0 = w0[widx];
                uint4 q1 = w1[widx];
                uint4 q2 = w2[widx];
                uint4 q3 = w3[widx];
                acc0 += dot8(q0, ha, hb);
                acc1 += dot8(q1, ha, hb);
                acc2 += dot8(q2, ha, hb);
                acc3 += dot8(q3, ha, hb);
            }
        }
        // ---- + W_in @ x ----
        {
            float xa = x_sh[2 * lane], xb = x_sh[2 * lane + 1];
            acc0 += winr[0]         * xa + winr[1]         * xb;
            acc1 += winr[D]         * xa + winr[D + 1]     * xb;
            acc2 += winr[2 * D]     * xa + winr[2 * D + 1] * xb;
            acc3 += winr[3 * D]     * xa + winr[3 * D + 1] * xb;
        }
        #pragma unroll
        for (int o = 16; o; o >>= 1) {
            acc0 += __shfl_xor_sync(0xffffffffu, acc0, o);
            acc1 += __shfl_xor_sync(0xffffffffu, acc1, o);
            acc2 += __shfl_xor_sync(0xffffffffu, acc2, o);
            acc3 += __shfl_xor_sync(0xffffffffu, acc3, o);
        }
        // ---- tanh, store h_{s+1}, aug broadcast ----
        float a0 = 0.f, a1 = 0.f, a2 = 0.f, a3 = 0.f;
        if (lane == 0) {
            float h0 = tanhf(acc0), h1 = tanhf(acc1), h2 = tanhf(acc2), h3 = tanhf(acc3);
            *(float4*)(d_h[(s + 1) & 1] + grow0) = make_float4(h0, h1, h2, h3);
            a0 = h0 * h0;   // even rows squared (grow0 % 2 == 0)
            a1 = h1;
            a2 = h2 * h2;
            a3 = h3;
        }
        a0 = __shfl_sync(0xffffffffu, a0, 0);
        a1 = __shfl_sync(0xffffffffu, a1, 0);
        a2 = __shfl_sync(0xffffffffu, a2, 0);
        a3 = __shfl_sync(0xffffffffu, a3, 0);

        // ---- fused readout partials: W_out @ aug(h_{s+1}) ----
        float p0 = wt[lane]              * a0 + wt[D + lane]          * a1 +
                   wt[2 * D + lane]      * a2 + wt[3 * D + lane]      * a3;
        float p1 = wt[32 + lane]         * a0 + wt[D + 32 + lane]     * a1 +
                   wt[2 * D + 32 + lane] * a2 + wt[3 * D + 32 + lane] * a3;
        ored[warp * 64 + lane]      = p0;
        ored[warp * 64 + 32 + lane] = p1;
        __syncthreads();
        if (tid < D) {
            float sum = 0.f;
            #pragma unroll
            for (int w = 0; w < WARPS; ++w) sum += ored[w * 64 + tid];
            atomicAdd(&d_osub[(s + 1) % 3][cta & 7][tid], sum);
        }
        gridbar();   // publishes h_{s+1} and the readout partial sums
    }
}

// ---------------- launch ----------------
extern "C" void kernel_launch(void* const* d_in, const int* in_sizes, int n_in,
                              void* d_out, int out_size) {
    const float* xin  = (const float*)d_in[0];
    const float* Win  = (const float*)d_in[1];
    const float* Whf  = (const float*)d_in[2];
    const float* Wout = (const float*)d_in[3];
    float* out = (float*)d_out;

    static bool attr_set = false;
    if (!attr_set) {
        cudaFuncSetAttribute(k_esn, cudaFuncAttributeMaxDynamicSharedMemorySize, SM_TOTAL);
        attr_set = true;
    }

    k_convert<<<4096, 256>>>(Whf);
    k_prep<<<1024, 256>>>(Wout, xin, out);
    k_esn<<<NB, NT, SM_TOTAL>>>(xin, Win, out);
}